// round 17
// baseline (speedup 1.0000x reference)
#include <cuda_runtime.h>
#include <cuda_fp16.h>
#include <math.h>
#include <stdint.h>

#define S_LEN    2048
#define D_MODEL  1024
#define N_HEADS  16
#define HEAD_DIM 64
#define BATCH    2
#define NTOK     (BATCH * S_LEN)   // 4096

// -------- scratch (device globals: no allocations allowed) --------
__device__ __half g_Qh[NTOK * D_MODEL];           // Q, attention A-frag order
__device__ __half g_Kh[NTOK * D_MODEL];           // K, attention B-frag order
__device__ __half g_Vh[NTOK * D_MODEL];           // V, attention B-frag order
__device__ __half g_Ch[NTOK * D_MODEL];           // ctx, out-GEMM A-frag order
__device__ __half g_Xh[NTOK * D_MODEL];           // x, GEMM A-frag order
__device__ __half g_Wh[4][D_MODEL * D_MODEL];     // weights, GEMM B-frag order
__device__ float  g_cos[S_LEN * 32];
__device__ float  g_sin[S_LEN * 32];

#define LOG2E 1.4426950408889634f

__device__ __forceinline__ unsigned h2u(float lo, float hi) {
    unsigned u;
    asm("cvt.rn.f16x2.f32 %0, %1, %2;" : "=r"(u) : "f"(hi), "f"(lo));
    return u;
}

__device__ __forceinline__ void mma16(float c[4], const unsigned a[4],
                                      unsigned b0, unsigned b1) {
    asm volatile(
        "mma.sync.aligned.m16n8k16.row.col.f32.f16.f16.f32 "
        "{%0,%1,%2,%3},{%4,%5,%6,%7},{%8,%9},{%0,%1,%2,%3};"
        : "+f"(c[0]), "+f"(c[1]), "+f"(c[2]), "+f"(c[3])
        : "r"(a[0]), "r"(a[1]), "r"(a[2]), "r"(a[3]), "r"(b0), "r"(b1));
}

// =================================================================
// Preround + permute to fp16 fragment layouts + RoPE table (merged).
// =================================================================
__global__ void preround_permute_kernel(const float* __restrict__ x,
                                        const float* __restrict__ Wq,
                                        const float* __restrict__ Wk,
                                        const float* __restrict__ Wv,
                                        const float* __restrict__ Wo)
{
    const int NXq = NTOK * (D_MODEL / 4);
    const int NWq = D_MODEL * (D_MODEL / 4);
    int idx = blockIdx.x * blockDim.x + threadIdx.x;
    if (idx < NXq) {
        int m = idx >> 8, k4 = idx & 255;
        float4 v = *(const float4*)&x[(size_t)m * D_MODEL + k4 * 4];
        int m_tile = m >> 7, mrow = m & 127;
        int mt = mrow >> 4, rr = mrow & 15, g = rr & 7, rh = rr >> 3;
        int kchunk = k4 >> 2, kk0 = (k4 & 3) * 4;
        int tig0 = (kk0 & 7) >> 1;
        int id0 = (kk0 < 8 ? 0 : 4) + rh * 2;
        __half* base = g_Xh + ((size_t)(m_tile * 64 + kchunk) * 8 + mt) * 256;
        *(unsigned*)(base + (size_t)(g * 4 + tig0) * 8 + id0)     = h2u(v.x, v.y);
        *(unsigned*)(base + (size_t)(g * 4 + tig0 + 1) * 8 + id0) = h2u(v.z, v.w);
    } else if (idx < NXq + 4 * NWq) {
        int r = idx - NXq;
        int w = r / NWq; r -= w * NWq;
        int n = r >> 8, k4 = r & 255;
        const float* ws[4] = {Wq, Wk, Wv, Wo};
        float4 v = *(const float4*)&ws[w][(size_t)n * D_MODEL + k4 * 4];
        int n_tile = n >> 7, nrow = n & 127;
        int nt = nrow >> 3, g = nrow & 7;
        int kchunk = k4 >> 2, kk0 = (k4 & 3) * 4;
        int tig0 = (kk0 & 7) >> 1;
        int id0 = (kk0 < 8) ? 0 : 2;
        __half* base = g_Wh[w] + ((size_t)(n_tile * 64 + kchunk) * 16 + nt) * 128;
        *(unsigned*)(base + (size_t)(g * 4 + tig0) * 4 + id0)     = h2u(v.x, v.y);
        *(unsigned*)(base + (size_t)(g * 4 + tig0 + 1) * 4 + id0) = h2u(v.z, v.w);
    } else if (idx < NXq + 4 * NWq + S_LEN * 32) {
        int i = idx - NXq - 4 * NWq;
        int pos = i >> 5;
        int f   = i & 31;
        float e    = (float)(2 * f) / 64.0f;
        float pw   = powf(10000.0f, e);
        float invf = 1.0f / pw;
        float angf = (float)pos * invf;
        double s, c;
        sincos((double)angf, &s, &c);
        g_cos[i] = (float)c;
        g_sin[i] = (float)s;
    }
}

// =================================================================
// Shared fp16 GEMM mainloop (both operands frag-order fp16).
// =================================================================
__device__ __forceinline__ void f16_gemm_main(
    const __half* __restrict__ Ag, const __half* __restrict__ Bg,
    float acc[4][8][4], __half* As, __half* Bs,
    int t, int mtb, int ntb, int lane)
{
#define LOADH(buf, s)                                                              \
    do {                                                                           \
        _Pragma("unroll")                                                          \
        for (int ii = 0; ii < 2; ii++) {                                           \
            int q = t + ii * 128;                                                  \
            unsigned da = (unsigned)__cvta_generic_to_shared(                      \
                As + (size_t)(buf) * 2048 + q * 8);                                \
            asm volatile("cp.async.cg.shared.global [%0], [%1], 16;"               \
                         :: "r"(da), "l"(Ag + (size_t)(s) * 2048 + q * 8));        \
            unsigned db = (unsigned)__cvta_generic_to_shared(                      \
                Bs + (size_t)(buf) * 2048 + q * 8);                                \
            asm volatile("cp.async.cg.shared.global [%0], [%1], 16;"               \
                         :: "r"(db), "l"(Bg + (size_t)(s) * 2048 + q * 8));        \
        }                                                                          \
        asm volatile("cp.async.commit_group;");                                    \
    } while (0)

    LOADH(0, 0);
    LOADH(1, 1);

    for (int i = 0; i < 64; i++) {
        asm volatile("cp.async.wait_group 1;");
        __syncthreads();
        if (i + 2 < 64) LOADH((i + 2) % 3, i + 2);
        const __half* Ab = As + (i % 3) * 2048;
        const __half* Bb = Bs + (i % 3) * 2048;

        unsigned af[4][4];
        uint2 bf[8];
#pragma unroll
        for (int mt = 0; mt < 4; mt++) {
            uint4 u = *(const uint4*)(Ab + (size_t)((mtb + mt) * 32 + lane) * 8);
            af[mt][0] = u.x; af[mt][1] = u.y; af[mt][2] = u.z; af[mt][3] = u.w;
        }
#pragma unroll
        for (int nt = 0; nt < 8; nt++)
            bf[nt] = *(const uint2*)(Bb + (size_t)((ntb + nt) * 32 + lane) * 4);
#pragma unroll
        for (int mt = 0; mt < 4; mt++)
#pragma unroll
            for (int nt = 0; nt < 8; nt++)
                mma16(acc[mt][nt], af[mt], bf[nt].x, bf[nt].y);
    }
#undef LOADH
}

// =================================================================
// QKV GEMM (fp16): 3 CTAs/SM target to cut wave quantization
// (768 CTAs / 444 slots = 1.73 waves vs 2.6 at occupancy 2).
// =================================================================
__global__ __launch_bounds__(128, 3) void qkv_gemm_kernel()
{
    __shared__ __align__(16) __half As[3 * 2048];
    __shared__ __align__(16) __half Bs[3 * 2048];

    const int z = blockIdx.z;
    const int t = threadIdx.x, warp = t >> 5, lane = t & 31;
    const int g = lane >> 2, tig = lane & 3;
    const int mtb = (warp >> 1) * 4;
    const int ntb = (warp & 1) * 8;
    const int wm = (warp >> 1) * 64;
    const int wn = (warp & 1) * 64;
    const int mb = blockIdx.y * 128, nb = blockIdx.x * 128;

    const __half* Ag = g_Xh + (size_t)blockIdx.y * 64 * 2048;
    const __half* Bg = g_Wh[z] + (size_t)blockIdx.x * 64 * 2048;

    const int rope_mode = (z < 2) ? 1 : 0;
    const float scale = (z == 0) ? 0.125f * LOG2E : 1.0f;

    float acc[4][8][4];
#pragma unroll
    for (int mt = 0; mt < 4; mt++)
#pragma unroll
        for (int nt = 0; nt < 8; nt++)
#pragma unroll
            for (int i = 0; i < 4; i++) acc[mt][nt][i] = 0.f;

    f16_gemm_main(Ag, Bg, acc, As, Bs, t, mtb, ntb, lane);

    const int bI   = mb >> 11;
    const int qt   = (mb & 2047) >> 7;
    const int tile = ((mb & 2047) + wm) >> 6;
    const int head = (nb + wn) >> 6;
    const int bh   = bI * N_HEADS + head;

#pragma unroll
    for (int mt = 0; mt < 4; mt++) {
        float rv[8][4];
#pragma unroll
        for (int nt = 0; nt < 8; nt++) {
            float v0 = acc[mt][nt][0], v1 = acc[mt][nt][1];
            float v2 = acc[mt][nt][2], v3 = acc[mt][nt][3];
            if (rope_mode) {
                int row = mb + wm + mt * 16 + g;
                int col = nb + wn + nt * 8 + 2 * tig;
                int fi = (col & 63) >> 1;
                int p0 = row & (S_LEN - 1);
                int p1 = (row + 8) & (S_LEN - 1);
                float c0 = g_cos[p0 * 32 + fi], s0 = g_sin[p0 * 32 + fi];
                float c1 = g_cos[p1 * 32 + fi], s1 = g_sin[p1 * 32 + fi];
                float r0 = v0 * c0 - v1 * s0, r1 = v0 * s0 + v1 * c0;
                float r2 = v2 * c1 - v3 * s1, r3 = v2 * s1 + v3 * c1;
                v0 = r0 * scale; v1 = r1 * scale;
                v2 = r2 * scale; v3 = r3 * scale;
            }
            rv[nt][0] = v0; rv[nt][1] = v1; rv[nt][2] = v2; rv[nt][3] = v3;
        }

        if (z == 0) {
            int wa = 2 * (warp >> 1) + (mt >> 1), bb = mt & 1;
            __half* base = g_Qh + ((size_t)bh * 16 + qt) * 8192
                         + (size_t)((wa * 2 + bb) * 4) * 256;
#pragma unroll
            for (int j = 0; j < 4; j++) {
                uint4 u;
                u.x = h2u(rv[2 * j][0],     rv[2 * j][1]);
                u.y = h2u(rv[2 * j][2],     rv[2 * j][3]);
                u.z = h2u(rv[2 * j + 1][0], rv[2 * j + 1][1]);
                u.w = h2u(rv[2 * j + 1][2], rv[2 * j + 1][3]);
                *(uint4*)(base + (size_t)(j * 32 + lane) * 8) = u;
            }
        } else if (z == 1) {
            __half* base = g_Kh + ((size_t)bh * 32 + tile) * 4096;
#pragma unroll
            for (int j = 0; j < 4; j++) {
                uint2 lo, hi;
                lo.x = h2u(rv[2 * j][0],     rv[2 * j][1]);
                lo.y = h2u(rv[2 * j + 1][0], rv[2 * j + 1][1]);
                hi.x = h2u(rv[2 * j][2],     rv[2 * j][3]);
                hi.y = h2u(rv[2 * j + 1][2], rv[2 * j + 1][3]);
                *(uint2*)(base + (size_t)((j * 8 + 2 * mt) * 32 + lane) * 4) = lo;
                *(uint2*)(base + (size_t)((j * 8 + 2 * mt + 1) * 32 + lane) * 4) = hi;
            }
        } else {
            __half* base = g_Vh + ((size_t)bh * 32 + tile) * 4096;
            const int tk = g >> 1, b1off = (g & 1) * 2;
#pragma unroll
            for (int nt = 0; nt < 8; nt++) {
                float u0 = __shfl_xor_sync(0xffffffffu, rv[nt][0], 4);
                float u1 = __shfl_xor_sync(0xffffffffu, rv[nt][1], 4);
                float u2 = __shfl_xor_sync(0xffffffffu, rv[nt][2], 4);
                float u3 = __shfl_xor_sync(0xffffffffu, rv[nt][3], 4);
                unsigned w0, w1;
                if ((g & 1) == 0) {
                    w0 = h2u(rv[nt][0], u0);
                    w1 = h2u(rv[nt][1], u1);
                } else {
                    w0 = h2u(u2, rv[nt][2]);
                    w1 = h2u(u3, rv[nt][3]);
                }
                unsigned o0 = (unsigned)((mt * 8 + nt) * 32 + 8 * tig + tk) * 4 + b1off;
                unsigned o1 = (unsigned)((mt * 8 + nt) * 32 + 8 * tig + 4 + tk) * 4 + b1off;
                *(unsigned*)(base + o0) = w0;
                *(unsigned*)(base + o1) = w1;
            }
        }
    }
}

// =================================================================
// Output GEMM (fp16): A = g_Ch (A-frag), B = Wo (B-frag). [R15 passing]
// =================================================================
__global__ __launch_bounds__(128, 2) void out_gemm_kernel(float* __restrict__ out)
{
    __shared__ __align__(16) __half As[3 * 2048];
    __shared__ __align__(16) __half Bs[3 * 2048];

    const int t = threadIdx.x, warp = t >> 5, lane = t & 31;
    const int g = lane >> 2, tig = lane & 3;
    const int mtb = (warp >> 1) * 4;
    const int ntb = (warp & 1) * 8;
    const int wm = (warp >> 1) * 64;
    const int wn = (warp & 1) * 64;
    const int mb = blockIdx.y * 128, nb = blockIdx.x * 128;

    const __half* Ag = g_Ch + (size_t)blockIdx.y * 64 * 2048;
    const __half* Bg = g_Wh[3] + (size_t)blockIdx.x * 64 * 2048;

    float acc[4][8][4];
#pragma unroll
    for (int mt = 0; mt < 4; mt++)
#pragma unroll
        for (int nt = 0; nt < 8; nt++)
#pragma unroll
            for (int i = 0; i < 4; i++) acc[mt][nt][i] = 0.f;

    f16_gemm_main(Ag, Bg, acc, As, Bs, t, mtb, ntb, lane);

#pragma unroll
    for (int mt = 0; mt < 4; mt++) {
#pragma unroll
        for (int nt = 0; nt < 8; nt++) {
            int row = mb + wm + mt * 16 + g;
            int col = nb + wn + nt * 8 + 2 * tig;
            *(float2*)&out[(size_t)row * D_MODEL + col] =
                make_float2(acc[mt][nt][0], acc[mt][nt][1]);
            *(float2*)&out[(size_t)(row + 8) * D_MODEL + col] =
                make_float2(acc[mt][nt][2], acc[mt][nt][3]);
        }
    }
}

// =================================================================
// FP16 flash attention, causal. Paired-tile schedule (uniform wave).
// l kept as per-thread alpha-scaled partials; single end reduction.
// =================================================================
__global__ __launch_bounds__(128, 2) void attn_f16(
    const __half* __restrict__ Qf, const __half* __restrict__ Kf,
    const __half* __restrict__ Vf, __half* __restrict__ Ch)
{
    __shared__ __align__(16) __half Ksf[4096];
    __shared__ __align__(16) __half Vsf[4096];

    const int t = threadIdx.x, warp = t >> 5, lane = t & 31;
    const int g = lane >> 2, tig = lane & 3;
    const int h  = blockIdx.y, b = blockIdx.z;
    const int w32 = warp * 32;
    const int bh = b * N_HEADS + h;
    const int NTILES = S_LEN / 128;      // 16

    for (int pass = 0; pass < 2; pass++) {
        const int tileI = pass == 0 ? (int)blockIdx.x
                                    : (NTILES - 1 - (int)blockIdx.x);
        const int qb = tileI * 128;

        const __half* Qblk = Qf + ((size_t)bh * 16 + tileI) * 8192;
        unsigned qf[2][4][4];
#pragma unroll
        for (int bb = 0; bb < 2; bb++)
#pragma unroll
            for (int kc = 0; kc < 4; kc++) {
                uint4 u = *(const uint4*)(Qblk +
                    (size_t)(((warp * 2 + bb) * 4 + kc) * 32 + lane) * 8);
                qf[bb][kc][0] = u.x; qf[bb][kc][1] = u.y;
                qf[bb][kc][2] = u.z; qf[bb][kc][3] = u.w;
            }

        float m_[2][2], l_[2][2];          // l_ = per-thread partials
        float o[2][8][4];
#pragma unroll
        for (int bb = 0; bb < 2; bb++) {
            m_[bb][0] = -1e30f; m_[bb][1] = -1e30f;
            l_[bb][0] = 0.f;    l_[bb][1] = 0.f;
#pragma unroll
            for (int nt = 0; nt < 8; nt++)
#pragma unroll
                for (int i = 0; i < 4; i++) o[bb][nt][i] = 0.f;
        }

        const int wrow_max = qb + w32 + 31;

        for (int kt = 0; kt <= qb + 64; kt += 64) {
            __syncthreads();
            const uint4* Kg = (const uint4*)(Kf + ((size_t)bh * 32 + (kt >> 6)) * 4096);
            const uint4* Vg = (const uint4*)(Vf + ((size_t)bh * 32 + (kt >> 6)) * 4096);
#pragma unroll
            for (int i = 0; i < 4; i++) {
                ((uint4*)Ksf)[t + i * 128] = Kg[t + i * 128];
                ((uint4*)Vsf)[t + i * 128] = Vg[t + i * 128];
            }
            __syncthreads();

            if (kt > wrow_max) continue;

            float s[2][8][4];
#pragma unroll
            for (int nt = 0; nt < 8; nt++) {
                float c0[4] = {0.f, 0.f, 0.f, 0.f};
                float c1[4] = {0.f, 0.f, 0.f, 0.f};
#pragma unroll
                for (int kc = 0; kc < 4; kc++) {
                    uint2 kb = *(const uint2*)(Ksf + (size_t)((kc * 8 + nt) * 32 + lane) * 4);
                    mma16(c0, qf[0][kc], kb.x, kb.y);
                    mma16(c1, qf[1][kc], kb.x, kb.y);
                }
#pragma unroll
                for (int i = 0; i < 4; i++) { s[0][nt][i] = c0[i]; s[1][nt][i] = c1[i]; }
            }

#pragma unroll
            for (int bb = 0; bb < 2; bb++) {
                const int r0 = qb + w32 + bb * 16 + g;
                const int r1 = r0 + 8;
                if (kt + 63 > qb + w32 + bb * 16) {
#pragma unroll
                    for (int nt = 0; nt < 8; nt++) {
                        int k0 = kt + nt * 8 + 2 * tig;
                        if (k0 > r0)     s[bb][nt][0] = -1e30f;
                        if (k0 + 1 > r0) s[bb][nt][1] = -1e30f;
                        if (k0 > r1)     s[bb][nt][2] = -1e30f;
                        if (k0 + 1 > r1) s[bb][nt][3] = -1e30f;
                    }
                }

                float mx0 = -1e30f, mx1 = -1e30f;
#pragma unroll
                for (int nt = 0; nt < 8; nt++) {
                    mx0 = fmaxf(mx0, fmaxf(s[bb][nt][0], s[bb][nt][1]));
                    mx1 = fmaxf(mx1, fmaxf(s[bb][nt][2], s[bb][nt][3]));
                }
                mx0 = fmaxf(mx0, __shfl_xor_sync(0xffffffffu, mx0, 1));
                mx0 = fmaxf(mx0, __shfl_xor_sync(0xffffffffu, mx0, 2));
                mx1 = fmaxf(mx1, __shfl_xor_sync(0xffffffffu, mx1, 1));
                mx1 = fmaxf(mx1, __shfl_xor_sync(0xffffffffu, mx1, 2));

                float nm0 = fmaxf(m_[bb][0], mx0), nm1 = fmaxf(m_[bb][1], mx1);
                float a0 = exp2f(m_[bb][0] - nm0), a1 = exp2f(m_[bb][1] - nm1);
                float sum0 = 0.f, sum1 = 0.f;
#pragma unroll
                for (int nt = 0; nt < 8; nt++) {
                    s[bb][nt][0] = exp2f(s[bb][nt][0] - nm0);
                    s[bb][nt][1] = exp2f(s[bb][nt][1] - nm0);
                    s[bb][nt][2] = exp2f(s[bb][nt][2] - nm1);
                    s[bb][nt][3] = exp2f(s[bb][nt][3] - nm1);
                    sum0 += s[bb][nt][0] + s[bb][nt][1];
                    sum1 += s[bb][nt][2] + s[bb][nt][3];
                }
                // per-thread partial l (row-uniform alphas make this exact)
                l_[bb][0] = l_[bb][0] * a0 + sum0;
                l_[bb][1] = l_[bb][1] * a1 + sum1;
                m_[bb][0] = nm0; m_[bb][1] = nm1;
#pragma unroll
                for (int nt = 0; nt < 8; nt++) {
                    o[bb][nt][0] *= a0; o[bb][nt][1] *= a0;
                    o[bb][nt][2] *= a1; o[bb][nt][3] *= a1;
                }
            }

#pragma unroll
            for (int kcp = 0; kcp < 4; kcp++) {
                unsigned pa[2][4];
#pragma unroll
                for (int bb = 0; bb < 2; bb++) {
                    pa[bb][0] = h2u(s[bb][2 * kcp][0],     s[bb][2 * kcp][1]);
                    pa[bb][1] = h2u(s[bb][2 * kcp][2],     s[bb][2 * kcp][3]);
                    pa[bb][2] = h2u(s[bb][2 * kcp + 1][0], s[bb][2 * kcp + 1][1]);
                    pa[bb][3] = h2u(s[bb][2 * kcp + 1][2], s[bb][2 * kcp + 1][3]);
                }
#pragma unroll
                for (int nt = 0; nt < 8; nt++) {
                    uint2 vb = *(const uint2*)(Vsf + (size_t)((kcp * 8 + nt) * 32 + lane) * 4);
                    mma16(o[0][nt], pa[0], vb.x, vb.y);
                    mma16(o[1][nt], pa[1], vb.x, vb.y);
                }
            }
        }

        // ---- epilogue: reduce l once, normalize, pack A-frag ctx ----
        const int m_tile = (b * S_LEN + qb) >> 7;
#pragma unroll
        for (int bb = 0; bb < 2; bb++) {
            float lr0 = l_[bb][0], lr1 = l_[bb][1];
            lr0 += __shfl_xor_sync(0xffffffffu, lr0, 1);
            lr0 += __shfl_xor_sync(0xffffffffu, lr0, 2);
            lr1 += __shfl_xor_sync(0xffffffffu, lr1, 1);
            lr1 += __shfl_xor_sync(0xffffffffu, lr1, 2);
            float inv0 = 1.0f / lr0, inv1 = 1.0f / lr1;
            const int mt = warp * 2 + bb;
            __half* base = g_Ch + ((size_t)(m_tile * 64 + h * 4) * 8 + mt) * 256
                         + (size_t)lane * 8;
#pragma unroll
            for (int kc = 0; kc < 4; kc++) {
                uint4 u;
                u.x = h2u(o[bb][2 * kc][0] * inv0,     o[bb][2 * kc][1] * inv0);
                u.y = h2u(o[bb][2 * kc][2] * inv1,     o[bb][2 * kc][3] * inv1);
                u.z = h2u(o[bb][2 * kc + 1][0] * inv0, o[bb][2 * kc + 1][1] * inv0);
                u.w = h2u(o[bb][2 * kc + 1][2] * inv1, o[bb][2 * kc + 1][3] * inv1);
                *(uint4*)(base + (size_t)kc * 2048) = u;
            }
        }
    }
}

// =================================================================
// Launch
// =================================================================
extern "C" void kernel_launch(void* const* d_in, const int* in_sizes, int n_in,
                              void* d_out, int out_size)
{
    const float* x  = (const float*)d_in[0];
    const float* Wq = (const float*)d_in[1];
    const float* Wk = (const float*)d_in[2];
    const float* Wv = (const float*)d_in[3];
    const float* Wo = (const float*)d_in[4];
    float* out = (float*)d_out;

    __half *Qh, *Kh, *Vh, *Ch;
    cudaGetSymbolAddress((void**)&Qh, g_Qh);
    cudaGetSymbolAddress((void**)&Kh, g_Kh);
    cudaGetSymbolAddress((void**)&Vh, g_Vh);
    cudaGetSymbolAddress((void**)&Ch, g_Ch);

    // 0: permute x + weights into fp16 fragment order + rope table
    int nthreads = NTOK * (D_MODEL / 4) + 4 * D_MODEL * (D_MODEL / 4) + S_LEN * 32;
    preround_permute_kernel<<<(nthreads + 255) / 256, 256>>>(x, Wq, Wk, Wv, Wo);

    // 1: QKV projections (fp16 mma, occupancy 3) -> fp16 frag-order Q/K/V
    qkv_gemm_kernel<<<dim3(D_MODEL / 128, NTOK / 128, 3), 128>>>();

    // 2: fp16 attention, paired-tile balanced schedule (256 CTAs)
    attn_f16<<<dim3(S_LEN / 256, N_HEADS, BATCH), 128>>>(Qh, Kh, Vh, Ch);

    // 3: output projection (fp16 mma) -> fp32 out
    out_gemm_kernel<<<dim3(D_MODEL / 128, NTOK / 128), 128>>>(out);
}